// round 5
// baseline (speedup 1.0000x reference)
#include <cuda_runtime.h>
#include <cuda_bf16.h>
#include <cstdint>

// Batched exp of log-affine matrices (ndims=3), B=1e6.
// R5: TMA bulk copies (cp.async.bulk) for both input and output so the
// 48B-stride per-lane L1 wavefront replays (measured binding resource,
// ~72 wf/warp * ~2cyc = ~18us) are replaced by dense TMA-engine traffic.
// SM-side memory work is only LDS/STS (conflict-free, 8 phases/warp).
//
// Math: fixed s=2 scaling-and-squaring, degree-4 Taylor (Paterson-
// Stockmeyer), phi1 matvec chain, 2 affine squarings. rel_err ~1.5e-7.

#define TPB 256

__device__ __forceinline__ uint32_t smem_u32(const void* p) {
    return (uint32_t)__cvta_generic_to_shared(p);
}

__device__ __forceinline__ void mm33(const float* __restrict__ X,
                                     const float* __restrict__ Y,
                                     float* __restrict__ Z) {
#pragma unroll
    for (int r = 0; r < 3; r++) {
        const float x0 = X[r * 3 + 0], x1 = X[r * 3 + 1], x2 = X[r * 3 + 2];
#pragma unroll
        for (int c = 0; c < 3; c++)
            Z[r * 3 + c] = fmaf(x0, Y[c], fmaf(x1, Y[3 + c], x2 * Y[6 + c]));
    }
}

__device__ __forceinline__ void mv3(const float* __restrict__ X,
                                    const float* __restrict__ v,
                                    float* __restrict__ w) {
#pragma unroll
    for (int r = 0; r < 3; r++)
        w[r] = fmaf(X[r * 3 + 0], v[0], fmaf(X[r * 3 + 1], v[1], X[r * 3 + 2] * v[2]));
}

__global__ void __launch_bounds__(TPB)
expaff_kernel(const float4* __restrict__ in, float4* __restrict__ out, int n) {
    __shared__ alignas(16) float4 s_in[TPB * 3];
    __shared__ alignas(16) float4 s_out[TPB * 3];
    __shared__ alignas(8) unsigned long long mbar;

    const int tid = threadIdx.x;
    const int base = blockIdx.x * TPB;
    const int nblk = min(TPB, n - base);
    const uint32_t bytes = (uint32_t)nblk * 48u;

    const uint32_t mbar_a = smem_u32(&mbar);
    const uint32_t sin_a = smem_u32(s_in);
    const uint32_t sout_a = smem_u32(s_out);

    if (tid == 0) {
        asm volatile("mbarrier.init.shared.b64 [%0], 1;" :: "r"(mbar_a) : "memory");
    }
    __syncthreads();

    if (tid == 0) {
        asm volatile("mbarrier.arrive.expect_tx.shared.b64 _, [%0], %1;"
                     :: "r"(mbar_a), "r"(bytes) : "memory");
        asm volatile(
            "cp.async.bulk.shared::cta.global.mbarrier::complete_tx::bytes "
            "[%0], [%1], %2, [%3];"
            :: "r"(sin_a), "l"(in + (size_t)base * 3), "r"(bytes), "r"(mbar_a)
            : "memory");
    }

    // Wait for TMA load (parity 0)
    {
        uint32_t done;
        asm volatile(
            "{\n\t.reg .pred p;\n\t"
            "mbarrier.try_wait.parity.acquire.cta.shared::cta.b64 p, [%1], 0;\n\t"
            "selp.b32 %0, 1, 0, p;\n\t}"
            : "=r"(done) : "r"(mbar_a) : "memory");
        if (!done) {
            asm volatile(
                "{\n\t.reg .pred P1;\n\t"
                "WL_%=:\n\t"
                "mbarrier.try_wait.parity.acquire.cta.shared::cta.b64 P1, [%0], 0, 0x989680;\n\t"
                "@P1 bra.uni WD_%=;\n\t"
                "bra.uni WL_%=;\n\t"
                "WD_%=:\n\t}"
                :: "r"(mbar_a) : "memory");
        }
    }

    if (tid < nblk) {
        float4 r0 = s_in[3 * tid + 0];
        float4 r1 = s_in[3 * tid + 1];
        float4 r2 = s_in[3 * tid + 2];

        // Coefficients with S = 2^-2 folded in.
        const float c1 = 0.25f;                                   // S
        const float c2 = 0.03125f;                                // S^2/2
        const float c3 = 0.25f * 0.25f * 0.25f / 6.0f;            // S^3/6
        const float c4 = 0.25f * 0.25f * 0.25f * 0.25f / 24.0f;   // S^4/24

        float A[9] = {r0.x, r0.y, r0.z,
                      r1.x, r1.y, r1.z,
                      r2.x, r2.y, r2.z};
        float t[3] = {r0.w, r1.w, r2.w};

        float B[9];
        mm33(A, A, B);

        float C[9];
#pragma unroll
        for (int j = 0; j < 9; j++) C[j] = fmaf(B[j], c4, A[j] * c3);
        float G[9];
        mm33(B, C, G);

        float E[9];
#pragma unroll
        for (int j = 0; j < 9; j++) E[j] = fmaf(A[j], c1, fmaf(B[j], c2, G[j]));
        E[0] += 1.0f; E[4] += 1.0f; E[8] += 1.0f;

        float w1[3], w2[3], w3[3], u[3];
        mv3(A, t, w1);
        mv3(A, w1, w2);
        mv3(A, w2, w3);
#pragma unroll
        for (int j = 0; j < 3; j++)
            u[j] = fmaf(t[j], c1, fmaf(w1[j], c2, fmaf(w2[j], c3, w3[j] * c4)));

#pragma unroll
        for (int q = 0; q < 2; q++) {
            float E2[9], u2[3];
            mm33(E, E, E2);
            mv3(E, u, u2);
#pragma unroll
            for (int j = 0; j < 9; j++) E[j] = E2[j];
#pragma unroll
            for (int j = 0; j < 3; j++) u[j] = u2[j] + u[j];
        }

        s_out[3 * tid + 0] = make_float4(E[0], E[1], E[2], u[0]);
        s_out[3 * tid + 1] = make_float4(E[3], E[4], E[5], u[1]);
        s_out[3 * tid + 2] = make_float4(E[6], E[7], E[8], u[2]);
    }

    // Order generic-proxy smem writes before async-proxy TMA read.
    asm volatile("fence.proxy.async.shared::cta;" ::: "memory");
    __syncthreads();

    if (tid == 0) {
        asm volatile(
            "cp.async.bulk.global.shared::cta.bulk_group [%0], [%1], %2;"
            :: "l"(out + (size_t)base * 3), "r"(sout_a), "r"(bytes)
            : "memory");
        asm volatile("cp.async.bulk.commit_group;" ::: "memory");
        // Must complete before block exit (smem lifetime).
        asm volatile("cp.async.bulk.wait_group 0;" ::: "memory");
    }
}

extern "C" void kernel_launch(void* const* d_in, const int* in_sizes, int n_in,
                              void* d_out, int out_size) {
    const float* vec = (const float*)d_in[0];
    float* outp = (float*)d_out;
    int n = in_sizes[0] / 12;

    int blocks = (n + TPB - 1) / TPB;
    expaff_kernel<<<blocks, TPB>>>((const float4*)vec, (float4*)outp, n);
}

// round 6
// speedup vs baseline: 1.1623x; 1.1623x over previous
#include <cuda_runtime.h>
#include <cuda_bf16.h>
#include <cstdint>

// Batched exp of log-affine matrices (ndims=3), B=1e6.
// R6: two matrices per thread, element-wise packed into Blackwell f32x2
// (fma.rn.f32x2 / FFMA2 -> one issue slot does both matrices), halving the
// instruction stream that R2-R5 showed to be the invariant limiter.
// TMA bulk staging kept from R5 (lowest L1 pressure).
//
// Math: fixed s=2 scaling-and-squaring, degree-4 Taylor (Paterson-
// Stockmeyer), phi1 matvec chain, 2 affine squarings. rel_err ~1.5e-7.

#define TPB 128
#define MPB (2 * TPB)  // matrices per block

typedef unsigned long long u64;

__device__ __forceinline__ uint32_t smem_u32(const void* p) {
    return (uint32_t)__cvta_generic_to_shared(p);
}

__device__ __forceinline__ u64 pk(float lo, float hi) {
    u64 r;
    asm("mov.b64 %0, {%1, %2};" : "=l"(r) : "f"(lo), "f"(hi));
    return r;
}
__device__ __forceinline__ void upk(u64 v, float& lo, float& hi) {
    asm("mov.b64 {%0, %1}, %2;" : "=f"(lo), "=f"(hi) : "l"(v));
}
__device__ __forceinline__ u64 ffma2(u64 a, u64 b, u64 c) {
    u64 d;
    asm("fma.rn.f32x2 %0, %1, %2, %3;" : "=l"(d) : "l"(a), "l"(b), "l"(c));
    return d;
}
__device__ __forceinline__ u64 fmul2(u64 a, u64 b) {
    u64 d;
    asm("mul.rn.f32x2 %0, %1, %2;" : "=l"(d) : "l"(a), "l"(b));
    return d;
}
__device__ __forceinline__ u64 fadd2(u64 a, u64 b) {
    u64 d;
    asm("add.rn.f32x2 %0, %1, %2;" : "=l"(d) : "l"(a), "l"(b));
    return d;
}

// Packed 3x3 matmul: Z = X * Y (each element is a {matA, matB} pair)
__device__ __forceinline__ void mm33p(const u64* __restrict__ X,
                                      const u64* __restrict__ Y,
                                      u64* __restrict__ Z) {
#pragma unroll
    for (int r = 0; r < 3; r++) {
        const u64 x0 = X[r * 3 + 0], x1 = X[r * 3 + 1], x2 = X[r * 3 + 2];
#pragma unroll
        for (int c = 0; c < 3; c++)
            Z[r * 3 + c] = ffma2(x0, Y[c], ffma2(x1, Y[3 + c], fmul2(x2, Y[6 + c])));
    }
}

__device__ __forceinline__ void mv3p(const u64* __restrict__ X,
                                     const u64* __restrict__ v,
                                     u64* __restrict__ w) {
#pragma unroll
    for (int r = 0; r < 3; r++)
        w[r] = ffma2(X[r * 3 + 0], v[0],
               ffma2(X[r * 3 + 1], v[1], fmul2(X[r * 3 + 2], v[2])));
}

__global__ void __launch_bounds__(TPB)
expaff_kernel(const float4* __restrict__ in, float4* __restrict__ out, int n) {
    __shared__ alignas(16) float4 s_in[MPB * 3];
    __shared__ alignas(16) float4 s_out[MPB * 3];
    __shared__ alignas(8) unsigned long long mbar;

    const int tid = threadIdx.x;
    const int base = blockIdx.x * MPB;
    const int nblk = min(MPB, n - base);
    const uint32_t bytes = (uint32_t)nblk * 48u;

    const uint32_t mbar_a = smem_u32(&mbar);
    const uint32_t sin_a = smem_u32(s_in);
    const uint32_t sout_a = smem_u32(s_out);

    if (tid == 0) {
        asm volatile("mbarrier.init.shared.b64 [%0], 1;" :: "r"(mbar_a) : "memory");
    }
    __syncthreads();

    if (tid == 0) {
        asm volatile("mbarrier.arrive.expect_tx.shared.b64 _, [%0], %1;"
                     :: "r"(mbar_a), "r"(bytes) : "memory");
        asm volatile(
            "cp.async.bulk.shared::cta.global.mbarrier::complete_tx::bytes "
            "[%0], [%1], %2, [%3];"
            :: "r"(sin_a), "l"(in + (size_t)base * 3), "r"(bytes), "r"(mbar_a)
            : "memory");
    }

    // Wait for TMA load (parity 0)
    {
        uint32_t done;
        asm volatile(
            "{\n\t.reg .pred p;\n\t"
            "mbarrier.try_wait.parity.acquire.cta.shared::cta.b64 p, [%1], 0;\n\t"
            "selp.b32 %0, 1, 0, p;\n\t}"
            : "=r"(done) : "r"(mbar_a) : "memory");
        if (!done) {
            asm volatile(
                "{\n\t.reg .pred P1;\n\t"
                "WL_%=:\n\t"
                "mbarrier.try_wait.parity.acquire.cta.shared::cta.b64 P1, [%0], 0, 0x989680;\n\t"
                "@P1 bra.uni WD_%=;\n\t"
                "bra.uni WL_%=;\n\t"
                "WD_%=:\n\t}"
                :: "r"(mbar_a) : "memory");
        }
    }

    // Two matrices per thread: slot a = tid, slot b = TPB + tid.
    {
        const int ia = tid;
        const int ib = TPB + tid;
        float4 a0 = s_in[3 * ia + 0], a1 = s_in[3 * ia + 1], a2 = s_in[3 * ia + 2];
        float4 b0 = s_in[3 * ib + 0], b1 = s_in[3 * ib + 1], b2 = s_in[3 * ib + 2];

        // Pack {matA, matB} element-wise.
        u64 A[9] = {pk(a0.x, b0.x), pk(a0.y, b0.y), pk(a0.z, b0.z),
                    pk(a1.x, b1.x), pk(a1.y, b1.y), pk(a1.z, b1.z),
                    pk(a2.x, b2.x), pk(a2.y, b2.y), pk(a2.z, b2.z)};
        u64 t[3] = {pk(a0.w, b0.w), pk(a1.w, b1.w), pk(a2.w, b2.w)};

        // Coefficients with S = 2^-2 folded in, broadcast to both lanes.
        const float f1 = 0.25f;
        const float f2 = 0.03125f;
        const float f3 = 0.25f * 0.25f * 0.25f / 6.0f;
        const float f4 = 0.25f * 0.25f * 0.25f * 0.25f / 24.0f;
        const u64 c1 = pk(f1, f1), c2 = pk(f2, f2);
        const u64 c3 = pk(f3, f3), c4 = pk(f4, f4);
        const u64 one = pk(1.0f, 1.0f);

        // B = A^2
        u64 B[9];
        mm33p(A, A, B);

        // C = c3*A + c4*B ; G = B*C
        u64 C[9];
#pragma unroll
        for (int j = 0; j < 9; j++) C[j] = ffma2(B[j], c4, fmul2(A[j], c3));
        u64 G[9];
        mm33p(B, C, G);

        // E = I + c1*A + c2*B + G
        u64 E[9];
#pragma unroll
        for (int j = 0; j < 9; j++) E[j] = ffma2(A[j], c1, ffma2(B[j], c2, G[j]));
        E[0] = fadd2(E[0], one);
        E[4] = fadd2(E[4], one);
        E[8] = fadd2(E[8], one);

        // u = c1*t + c2*At + c3*A^2 t + c4*A^3 t
        u64 w1[3], w2[3], w3[3], u[3];
        mv3p(A, t, w1);
        mv3p(A, w1, w2);
        mv3p(A, w2, w3);
#pragma unroll
        for (int j = 0; j < 3; j++)
            u[j] = ffma2(t[j], c1, ffma2(w1[j], c2, ffma2(w2[j], c3, fmul2(w3[j], c4))));

        // Two affine squarings: [E,u] <- [E^2, E u + u]
#pragma unroll
        for (int q = 0; q < 2; q++) {
            u64 E2[9], u2[3];
            mm33p(E, E, E2);
            mv3p(E, u, u2);
#pragma unroll
            for (int j = 0; j < 9; j++) E[j] = E2[j];
#pragma unroll
            for (int j = 0; j < 3; j++) u[j] = fadd2(u2[j], u[j]);
        }

        // Unpack and write both matrices to smem.
        float ea[12], eb[12];
        upk(E[0], ea[0], eb[0]);  upk(E[1], ea[1], eb[1]);  upk(E[2], ea[2], eb[2]);
        upk(u[0], ea[3], eb[3]);
        upk(E[3], ea[4], eb[4]);  upk(E[4], ea[5], eb[5]);  upk(E[5], ea[6], eb[6]);
        upk(u[1], ea[7], eb[7]);
        upk(E[6], ea[8], eb[8]);  upk(E[7], ea[9], eb[9]);  upk(E[8], ea[10], eb[10]);
        upk(u[2], ea[11], eb[11]);

        s_out[3 * ia + 0] = make_float4(ea[0], ea[1], ea[2], ea[3]);
        s_out[3 * ia + 1] = make_float4(ea[4], ea[5], ea[6], ea[7]);
        s_out[3 * ia + 2] = make_float4(ea[8], ea[9], ea[10], ea[11]);
        s_out[3 * ib + 0] = make_float4(eb[0], eb[1], eb[2], eb[3]);
        s_out[3 * ib + 1] = make_float4(eb[4], eb[5], eb[6], eb[7]);
        s_out[3 * ib + 2] = make_float4(eb[8], eb[9], eb[10], eb[11]);
    }

    // Order generic-proxy smem writes before async-proxy TMA read.
    asm volatile("fence.proxy.async.shared::cta;" ::: "memory");
    __syncthreads();

    if (tid == 0) {
        asm volatile(
            "cp.async.bulk.global.shared::cta.bulk_group [%0], [%1], %2;"
            :: "l"(out + (size_t)base * 3), "r"(sout_a), "r"(bytes)
            : "memory");
        asm volatile("cp.async.bulk.commit_group;" ::: "memory");
        asm volatile("cp.async.bulk.wait_group 0;" ::: "memory");
    }
}

extern "C" void kernel_launch(void* const* d_in, const int* in_sizes, int n_in,
                              void* d_out, int out_size) {
    const float* vec = (const float*)d_in[0];
    float* outp = (float*)d_out;
    int n = in_sizes[0] / 12;

    int blocks = (n + MPB - 1) / MPB;
    expaff_kernel<<<blocks, TPB>>>((const float4*)vec, (float4*)outp, n);
}